// round 16
// baseline (speedup 1.0000x reference)
#include <cuda_runtime.h>
#include <cstdint>

// Problem constants (from reference)
#define NNODES 100000
#define NEDGES 600000
#define NHEADS 8
#define NDIM   16
#define NTGT   20000
#define ROW    (NHEADS * NDIM)   // 128 floats per node/edge row

// Scratch: per-node aggregated features + "is-target" flag.
// Flags are set-only and the target set is identical every launch; nft target
// rows are re-zeroed at the start of every launch by k_prep.
__device__ float         g_nft[(size_t)NNODES * ROW];
__device__ unsigned char g_flag[NNODES];

// ---------------------------------------------------------------------------
// K1: zero nft rows for target nodes, set flags. 1 warp per target.
// ---------------------------------------------------------------------------
__global__ void k_prep(const int* __restrict__ target_idx, int T) {
    int w = (blockIdx.x * blockDim.x + threadIdx.x) >> 5;
    int lane = threadIdx.x & 31;
    if (w >= T) return;
    int n = target_idx[w];
    float4 z = make_float4(0.f, 0.f, 0.f, 0.f);
    *reinterpret_cast<float4*>(&g_nft[(size_t)n * ROW + lane * 4]) = z;
    if (lane == 0) g_flag[n] = 1;
}

// ---------------------------------------------------------------------------
// K2: 4 edges per warp; load i covers edge i's FULL contiguous 512B row with
// all 32 lanes (lane = one float4 chunk; head = lane>>2, slot = lane&3).
// All memory (dst, 4 eft rows, 4 node rows, 4 flag bytes) issued up front in
// one MLP window. Softmax over heads, coalesced 128B 'a' store (.cs), then
// predicated vec4 RED scatter into target nodes (~18% of edges).
// ---------------------------------------------------------------------------
__global__ void __launch_bounds__(512) k_edge(const float* __restrict__ node,
                                              const float* __restrict__ eft,
                                              const int*   __restrict__ dst,
                                              float* __restrict__ a_out) {
    const int lane = threadIdx.x & 31;
    const int warp = (blockIdx.x * blockDim.x + threadIdx.x) >> 5;

    // 4 destination indices for this warp's edges (16B broadcast load)
    const int4 d4 = __ldg(reinterpret_cast<const int4*>(dst) + warp);
    const int d[4] = {d4.x, d4.y, d4.z, d4.w};

    const int e0 = warp * 4;

    // 8 fully-coalesced 512B row loads + 4 flag bytes, all in flight together
    float4 ef[4], nd[4];
#pragma unroll
    for (int i = 0; i < 4; i++)
        ef[i] = __ldcs(reinterpret_cast<const float4*>(eft + (size_t)(e0 + i) * ROW) + lane);
#pragma unroll
    for (int i = 0; i < 4; i++)
        nd[i] = __ldg(reinterpret_cast<const float4*>(node + (size_t)d[i] * ROW) + lane);
    unsigned char fl[4];
#pragma unroll
    for (int i = 0; i < 4; i++) fl[i] = g_flag[d[i]];

    // per-edge: slot-reduce dot, then softmax across 8 heads.
    // (|sim| <= ~25 so expf is safe in fp32 without max-subtraction)
    float a[4];
#pragma unroll
    for (int i = 0; i < 4; i++) {
        float s = ef[i].x * nd[i].x + ef[i].y * nd[i].y
                + ef[i].z * nd[i].z + ef[i].w * nd[i].w;
        s += __shfl_xor_sync(0xFFFFFFFFu, s, 1);
        s += __shfl_xor_sync(0xFFFFFFFFu, s, 2);   // sim[head] in 4-lane group
        float ex  = __expf(s);
        float sum = ex;
        sum += __shfl_xor_sync(0xFFFFFFFFu, sum, 4);
        sum += __shfl_xor_sync(0xFFFFFFFFu, sum, 8);
        sum += __shfl_xor_sync(0xFFFFFFFFu, sum, 16);  // sum over all 8 heads
        a[i] = ex / sum;
    }

    // a output: lane writes a[(e0 + slot)*8 + head] -> one coalesced 128B
    // line per warp, streaming store (write-once data, keep L2 for node).
    {
        const int s = lane & 3, h = lane >> 2;
        float v = a[0];
        v = (s == 1) ? a[1] : v;
        v = (s == 2) ? a[2] : v;
        v = (s == 3) ? a[3] : v;
        __stcs(&a_out[(size_t)warp * 32 + s * 8 + h], v);
    }

    // scatter only into nodes that will actually be read (targets, ~18%).
    // Each predicated RED covers edge i's contiguous 512B row (4 lines).
#pragma unroll
    for (int i = 0; i < 4; i++) {
        if (fl[i]) {
            float* p = &g_nft[(size_t)d[i] * ROW + lane * 4];
            asm volatile("red.global.add.v4.f32 [%0], {%1,%2,%3,%4};"
                         :: "l"(p),
                            "f"(ef[i].x * a[i]), "f"(ef[i].y * a[i]),
                            "f"(ef[i].z * a[i]), "f"(ef[i].w * a[i])
                         : "memory");
        }
    }
}

// ---------------------------------------------------------------------------
// K3: gather targets, +1e-15, L2-normalize over heads per (t, d), write out.
// 1 warp per target.
// ---------------------------------------------------------------------------
__global__ void k_out(const int* __restrict__ target_idx,
                      float* __restrict__ out, int T) {
    int w = (blockIdx.x * blockDim.x + threadIdx.x) >> 5;
    if (w >= T) return;
    int lane = threadIdx.x & 31;
    int n = target_idx[w];

    float4 x = *reinterpret_cast<const float4*>(&g_nft[(size_t)n * ROW + lane * 4]);
    x.x += 1e-15f; x.y += 1e-15f; x.z += 1e-15f; x.w += 1e-15f;

    float4 sq = make_float4(x.x * x.x, x.y * x.y, x.z * x.z, x.w * x.w);
#pragma unroll
    for (int off = 4; off <= 16; off <<= 1) {
        sq.x += __shfl_xor_sync(0xFFFFFFFFu, sq.x, off);
        sq.y += __shfl_xor_sync(0xFFFFFFFFu, sq.y, off);
        sq.z += __shfl_xor_sync(0xFFFFFFFFu, sq.z, off);
        sq.w += __shfl_xor_sync(0xFFFFFFFFu, sq.w, off);
    }
    float4 r;
    r.x = x.x / fmaxf(sqrtf(sq.x), 1e-12f);
    r.y = x.y / fmaxf(sqrtf(sq.y), 1e-12f);
    r.z = x.z / fmaxf(sqrtf(sq.z), 1e-12f);
    r.w = x.w / fmaxf(sqrtf(sq.w), 1e-12f);

    *reinterpret_cast<float4*>(&out[(size_t)w * ROW + lane * 4]) = r;
}

// ---------------------------------------------------------------------------
// Inputs (metadata order): node [N,H,D] f32, eft [E,H,D] f32, dst [E] i32,
// target_idx [T] i32. Output: concat(out [T,H,D], a [E,H]) as f32.
// ---------------------------------------------------------------------------
extern "C" void kernel_launch(void* const* d_in, const int* in_sizes, int n_in,
                              void* d_out, int out_size) {
    const float* node       = (const float*)d_in[0];
    const float* eft        = (const float*)d_in[1];
    const int*   dst        = (const int*)d_in[2];
    const int*   target_idx = (const int*)d_in[3];

    float* out   = (float*)d_out;                       // [T,H,D]
    float* a_out = (float*)d_out + (size_t)NTGT * ROW;  // [E,H]

    // K1: 1 warp per target
    k_prep<<<(NTGT * 32 + 255) / 256, 256>>>(target_idx, NTGT);
    // K2: 4 edges/warp, 512-thread CTAs -> 64 edges per CTA (600000/64 = 9375)
    k_edge<<<NEDGES / 64, 512>>>(node, eft, dst, a_out);
    // K3: 1 warp per target
    k_out<<<(NTGT * 32 + 255) / 256, 256>>>(target_idx, out, NTGT);
}

// round 17
// speedup vs baseline: 1.0767x; 1.0767x over previous
#include <cuda_runtime.h>
#include <cstdint>

// Problem constants (from reference)
#define NNODES 100000
#define NEDGES 600000
#define NHEADS 8
#define NDIM   16
#define NTGT   20000
#define ROW    (NHEADS * NDIM)   // 128 floats per node/edge row

#define EDGES_PER_CTA 64         // 64 x 512B = 32KB smem stage
#define EDGES_PER_WARP 8         // 8 warps x 8 edges = 64

// Scratch: per-node aggregated features + "is-target" flag.
// Flags are set-only and the target set is identical every launch; nft target
// rows are re-zeroed at the start of every launch by k_prep.
__device__ float         g_nft[(size_t)NNODES * ROW];
__device__ unsigned char g_flag[NNODES];

// ---------------------------------------------------------------------------
// K1: zero nft rows for target nodes, set flags. 1 warp per target.
// ---------------------------------------------------------------------------
__global__ void k_prep(const int* __restrict__ target_idx, int T) {
    int w = (blockIdx.x * blockDim.x + threadIdx.x) >> 5;
    int lane = threadIdx.x & 31;
    if (w >= T) return;
    int n = target_idx[w];
    float4 z = make_float4(0.f, 0.f, 0.f, 0.f);
    *reinterpret_cast<float4*>(&g_nft[(size_t)n * ROW + lane * 4]) = z;
    if (lane == 0) g_flag[n] = 1;
}

// ---------------------------------------------------------------------------
// helpers: smem address + mbarrier ops (one-shot, phase 0)
// ---------------------------------------------------------------------------
__device__ __forceinline__ uint32_t smem_u32(const void* p) {
    uint32_t a;
    asm("{ .reg .u64 t; cvta.to.shared.u64 t, %1; cvt.u32.u64 %0, t; }"
        : "=r"(a) : "l"(p));
    return a;
}

// ---------------------------------------------------------------------------
// K2: one CTA per 64 contiguous edges. eft rows staged into smem by ONE
// cp.async.bulk (TMA engine hides the DRAM latency across co-resident CTAs);
// node rows gathered from L2 with LDG as before. Each warp runs the proven
// 4-edge batch body twice, reading ef from smem (conflict-free: row-major
// 512B rows, lane = one float4).
// ---------------------------------------------------------------------------
__global__ void __launch_bounds__(256) k_edge(const float* __restrict__ node,
                                              const float* __restrict__ eft,
                                              const int*   __restrict__ dst,
                                              float* __restrict__ a_out) {
    __shared__ alignas(128) float4 s_ef[EDGES_PER_CTA * (ROW / 4)];  // 32 KB
    __shared__ alignas(8) uint64_t s_mbar;

    const int tid  = threadIdx.x;
    const int lane = tid & 31;
    const int wid  = tid >> 5;                      // 0..7
    const int b    = blockIdx.x;
    const int ebase = b * EDGES_PER_CTA;            // CTA's first edge

    const uint32_t mbar = smem_u32(&s_mbar);

    if (tid == 0) {
        asm volatile("mbarrier.init.shared.b64 [%0], %1;" :: "r"(mbar), "r"(1) : "memory");
    }
    __syncthreads();

    if (tid == 0) {
        const uint32_t bytes = EDGES_PER_CTA * ROW * 4;   // 32768
        asm volatile("mbarrier.arrive.expect_tx.shared.b64 _, [%0], %1;"
                     :: "r"(mbar), "r"(bytes) : "memory");
        asm volatile("cp.async.bulk.shared::cluster.global.mbarrier::complete_tx::bytes "
                     "[%0], [%1], %2, [%3];"
                     :: "r"(smem_u32(s_ef)),
                        "l"(eft + (size_t)ebase * ROW),
                        "r"(bytes), "r"(mbar)
                     : "memory");
    }

    // While the bulk copy is in flight: this warp's dst ids + first node batch.
    const int we0 = ebase + wid * EDGES_PER_WARP;   // warp's first edge
    const int4 da = __ldg(reinterpret_cast<const int4*>(dst) + (we0 >> 2));
    const int4 db = __ldg(reinterpret_cast<const int4*>(dst) + (we0 >> 2) + 1);
    const int d[8] = {da.x, da.y, da.z, da.w, db.x, db.y, db.z, db.w};

    float4 nd0[4];
#pragma unroll
    for (int i = 0; i < 4; i++)
        nd0[i] = __ldg(reinterpret_cast<const float4*>(node + (size_t)d[i] * ROW) + lane);

    // Wait for the eft stage (acquire orders the smem reads below).
    {
        uint32_t parity = 0;
        asm volatile(
            "{\n\t"
            ".reg .pred P1;\n\t"
            "WAIT_LOOP_%=:\n\t"
            "mbarrier.try_wait.parity.acquire.cta.shared::cta.b64 P1, [%0], %1, 0x989680;\n\t"
            "@P1 bra.uni WAIT_DONE_%=;\n\t"
            "bra.uni WAIT_LOOP_%=;\n\t"
            "WAIT_DONE_%=:\n\t"
            "}" :: "r"(mbar), "r"(parity) : "memory");
    }

    // Two 4-edge batches (R3-proven body; ef from smem).
#pragma unroll
    for (int it = 0; it < 2; it++) {
        const int lb = wid * EDGES_PER_WARP + it * 4;   // local edge base in smem
        float4 ef[4], nd[4];
#pragma unroll
        for (int i = 0; i < 4; i++)
            ef[i] = s_ef[(lb + i) * (ROW / 4) + lane];
        if (it == 0) {
#pragma unroll
            for (int i = 0; i < 4; i++) nd[i] = nd0[i];
        } else {
#pragma unroll
            for (int i = 0; i < 4; i++)
                nd[i] = __ldg(reinterpret_cast<const float4*>(node + (size_t)d[4 + i] * ROW) + lane);
        }
        const int* dd = d + it * 4;

        float a[4];
#pragma unroll
        for (int i = 0; i < 4; i++) {
            float s = ef[i].x * nd[i].x + ef[i].y * nd[i].y
                    + ef[i].z * nd[i].z + ef[i].w * nd[i].w;
            s += __shfl_xor_sync(0xFFFFFFFFu, s, 1);
            s += __shfl_xor_sync(0xFFFFFFFFu, s, 2);     // sim[head]
            float ex  = __expf(s);                       // |sim| small: no max-sub
            float sum = ex;
            sum += __shfl_xor_sync(0xFFFFFFFFu, sum, 4);
            sum += __shfl_xor_sync(0xFFFFFFFFu, sum, 8);
            sum += __shfl_xor_sync(0xFFFFFFFFu, sum, 16);
            a[i] = ex / sum;
        }

        // a output: one coalesced 128B line per batch.
        // index = (E0 + slot)*8 + head, E0 = we0 + it*4
        {
            const int s = lane & 3, h = lane >> 2;
            float v = a[0];
            v = (s == 1) ? a[1] : v;
            v = (s == 2) ? a[2] : v;
            v = (s == 3) ? a[3] : v;
            a_out[(size_t)(we0 + it * 4) * 8 + s * 8 + h] = v;
        }

        // predicated vec4 RED scatter into target nodes (~18% of edges)
#pragma unroll
        for (int i = 0; i < 4; i++) {
            if (g_flag[dd[i]]) {
                float* p = &g_nft[(size_t)dd[i] * ROW + lane * 4];
                asm volatile("red.global.add.v4.f32 [%0], {%1,%2,%3,%4};"
                             :: "l"(p),
                                "f"(ef[i].x * a[i]), "f"(ef[i].y * a[i]),
                                "f"(ef[i].z * a[i]), "f"(ef[i].w * a[i])
                             : "memory");
            }
        }
    }
}

// ---------------------------------------------------------------------------
// K3: gather targets, +1e-15, L2-normalize over heads per (t, d), write out.
// 1 warp per target.
// ---------------------------------------------------------------------------
__global__ void k_out(const int* __restrict__ target_idx,
                      float* __restrict__ out, int T) {
    int w = (blockIdx.x * blockDim.x + threadIdx.x) >> 5;
    if (w >= T) return;
    int lane = threadIdx.x & 31;
    int n = target_idx[w];

    float4 x = *reinterpret_cast<const float4*>(&g_nft[(size_t)n * ROW + lane * 4]);
    x.x += 1e-15f; x.y += 1e-15f; x.z += 1e-15f; x.w += 1e-15f;

    float4 sq = make_float4(x.x * x.x, x.y * x.y, x.z * x.z, x.w * x.w);
#pragma unroll
    for (int off = 4; off <= 16; off <<= 1) {
        sq.x += __shfl_xor_sync(0xFFFFFFFFu, sq.x, off);
        sq.y += __shfl_xor_sync(0xFFFFFFFFu, sq.y, off);
        sq.z += __shfl_xor_sync(0xFFFFFFFFu, sq.z, off);
        sq.w += __shfl_xor_sync(0xFFFFFFFFu, sq.w, off);
    }
    float4 r;
    r.x = x.x / fmaxf(sqrtf(sq.x), 1e-12f);
    r.y = x.y / fmaxf(sqrtf(sq.y), 1e-12f);
    r.z = x.z / fmaxf(sqrtf(sq.z), 1e-12f);
    r.w = x.w / fmaxf(sqrtf(sq.w), 1e-12f);

    *reinterpret_cast<float4*>(&out[(size_t)w * ROW + lane * 4]) = r;
}

// ---------------------------------------------------------------------------
// Inputs (metadata order): node [N,H,D] f32, eft [E,H,D] f32, dst [E] i32,
// target_idx [T] i32. Output: concat(out [T,H,D], a [E,H]) as f32.
// ---------------------------------------------------------------------------
extern "C" void kernel_launch(void* const* d_in, const int* in_sizes, int n_in,
                              void* d_out, int out_size) {
    const float* node       = (const float*)d_in[0];
    const float* eft        = (const float*)d_in[1];
    const int*   dst        = (const int*)d_in[2];
    const int*   target_idx = (const int*)d_in[3];

    float* out   = (float*)d_out;                       // [T,H,D]
    float* a_out = (float*)d_out + (size_t)NTGT * ROW;  // [E,H]

    // K1: 1 warp per target
    k_prep<<<(NTGT * 32 + 255) / 256, 256>>>(target_idx, NTGT);
    // K2: one CTA per 64 edges (600000 / 64 = 9375)
    k_edge<<<NEDGES / EDGES_PER_CTA, 256>>>(node, eft, dst, a_out);
    // K3: 1 warp per target
    k_out<<<(NTGT * 32 + 255) / 256, 256>>>(target_idx, out, NTGT);
}